// round 8
// baseline (speedup 1.0000x reference)
#include <cuda_runtime.h>
#include <cuda_bf16.h>

// ZBL basis: per-edge screened Coulomb repulsion with polynomial cutoff,
// scatter-summed into receiver nodes.
//
// Inputs (metadata order):
//   d_in[0]: x               float32 [E, 1]   (E = 3,200,000)
//   d_in[1]: node_attrs      float32 [N, 10]  (N = 100,000)
//   d_in[2]: edge_index      int32   [2, E]
//   d_in[3]: atomic_numbers  int32   [10]
//   d_in[4]: covalent_radii  float32 [119]
// Output: V_ZBL float32 [N]
//
// HW model (validated R6/R7): per-SM LSU wavefront throughput floor
// (~122 cyc / 128 edges: RED ~80, u8 gathers ~28, LDG ~12), but observed is
// ~1.6x above it -> latency-exposed at 32 warps/SM. This revision packs the
// element table to NIBBLES (10 elems < 16): 50KB table + 38.4KB replicated
// LUTs = 88.6KB smem -> 2 blocks x 1024 thr / SM = 64 warps. launch_bounds
// caps regs at 32 (RF exactly fits); unroll reduced to 2 edges/thread.

#define MAX_NODES 100352   // >= N, even, multiple of 32
#define PACKED_N  (MAX_NODES / 2)   // 50176 bytes, multiple of 16
#define N_ELEMS   10
#define NPAIR     (N_ELEMS * N_ELEMS)
#define EDGE_GRID 296      // 2 blocks/SM x 148 SMs: one full wave
#define NT        1024

__device__ unsigned char g_e4[PACKED_N];   // 2 nodes/byte: elem idx in nibble

__device__ __forceinline__ float ex2f(float a) {
    float r; asm("ex2.approx.f32 %0, %1;" : "=f"(r) : "f"(a)); return r;
}
__device__ __forceinline__ float frcpf(float a) {
    float r; asm("rcp.approx.f32 %0, %1;" : "=f"(r) : "f"(a)); return r;
}

// Predicated no-return global float add; no memory clobber (write-only out).
__device__ __forceinline__ void red_add_if(float* addr, float val, float rr) {
    asm volatile(
        "{\n\t"
        ".reg .pred p;\n\t"
        "setp.lt.f32 p, %1, 0f3F800000;\n\t"   // rr < 1.0f
        "@p red.global.add.f32 [%0], %2;\n\t"
        "}"
        :: "l"(addr), "f"(rr), "f"(val));
}

// ---------------------------------------------------------------------------
// Node prep: each thread handles TWO nodes -> one packed byte (no write race).
// Also zeros the output.
// ---------------------------------------------------------------------------
__global__ void node_prep_kernel(const float* __restrict__ attrs,
                                 float* __restrict__ out,
                                 int n_nodes, int out_n) {
    __shared__ float s[512 * N_ELEMS];      // 20KB staging
    int base = blockIdx.x * 512;            // node base (2 nodes per thread)
    int nloc = n_nodes - base;
    if (nloc > 512) nloc = 512;
    if (nloc > 0) {
        int total = nloc * N_ELEMS;
        const float* src = attrs + (size_t)base * N_ELEMS;
        int nv4 = total >> 2;
        const float4* s4 = (const float4*)src;
        float4* d4 = (float4*)s;
        for (int k = threadIdx.x; k < nv4; k += 256) d4[k] = s4[k];
        for (int k = (nv4 << 2) + threadIdx.x; k < total; k += 256)
            s[k] = src[k];
    }
    __syncthreads();

    int t = threadIdx.x;                     // handles local nodes 2t, 2t+1
    int n0 = 2 * t, n1 = 2 * t + 1;
    unsigned char packed = 0;
#pragma unroll
    for (int half = 0; half < 2; half++) {
        int nl = half ? n1 : n0;
        if (nl < nloc) {
            const float* a = s + nl * N_ELEMS;
            int best = 0;
            float bv = a[0];
#pragma unroll
            for (int j = 1; j < N_ELEMS; j++) {
                float v = a[j];
                if (v > bv) { bv = v; best = j; }
            }
            packed |= (unsigned char)(best << (half * 4));
        }
    }
    int byte_idx = (base >> 1) + t;
    if (n0 < nloc) g_e4[byte_idx] = packed;

    // zero outputs: 2 per thread
    int o0 = base + n0, o1 = base + n1;
    if (o0 < out_n) out[o0] = 0.0f;
    if (o1 < out_n) out[o1] = 0.0f;
}

// ---------------------------------------------------------------------------
// Edge kernel
// ---------------------------------------------------------------------------
__device__ __forceinline__ void process_edge(
    int s, int r, float xi, int lane,
    const unsigned char* __restrict__ s_e4,
    const float* __restrict__ s_irm,   // replicated: [idx*32 + lane]
    const float* __restrict__ s_ia,
    const float* __restrict__ s_pf,
    float* __restrict__ out)
{
    int eu = (s_e4[s >> 1] >> ((s & 1) << 2)) & 15;
    int ev = (s_e4[r >> 1] >> ((r & 1) << 2)) & 15;
    int idx = ((eu * N_ELEMS + ev) << 5) + lane;   // bank==lane: conflict-free
    float inv_rmax = s_irm[idx];
    float invA     = s_ia[idx];
    float pref     = s_pf[idx];

    float rr = xi * inv_rmax;
    float t  = xi * invA;

    // exp(-c*t) as ex2((-c*log2e)*t); constants folded at compile time
    const float K0 = -3.2f    * 1.44269504f;
    const float K1 = -0.9423f * 1.44269504f;
    const float K2 = -0.4028f * 1.44269504f;
    const float K3 = -0.2016f * 1.44269504f;
    float phi = 0.1818f  * ex2f(K0 * t)
              + 0.5099f  * ex2f(K1 * t)
              + 0.2802f  * ex2f(K2 * t)
              + 0.02817f * ex2f(K3 * t);

    // polynomial envelope, p=6: 1 - 28 r^6 + 48 r^7 - 21 r^8
    float r2 = rr * rr;
    float r3 = r2 * rr;
    float r6 = r3 * r3;
    float env = fmaf(-28.0f, r6, 1.0f);
    env = fmaf(48.0f, r6 * rr, env);
    env = fmaf(-21.0f, r6 * r2, env);

    float val = pref * phi * frcpf(xi) * env;
    red_add_if(out + r, val, rr);
}

__global__ void __launch_bounds__(NT, 2)
edge_kernel(const float* __restrict__ x,
            const int* __restrict__ ei,
            const int* __restrict__ atomic_numbers,
            const float* __restrict__ radii_g,
            float* __restrict__ out,
            int n_edges, int n_nodes) {
    extern __shared__ char smem[];
    float* s_irm = (float*)smem;                 // NPAIR*32 (bank-replicated)
    float* s_ia  = s_irm + NPAIR * 32;
    float* s_pf  = s_ia + NPAIR * 32;
    unsigned char* s_e4 = (unsigned char*)(s_pf + NPAIR * 32);

    int tid = threadIdx.x;
    int lane = tid & 31;

    // Build bank-replicated SoA pair LUTs (entry idx at [idx*32 + c]).
    if (tid < NPAIR) {
        int i = tid / N_ELEMS, j = tid % N_ELEMS;
        int Zi = atomic_numbers[i], Zj = atomic_numbers[j];
        float Zif = (float)Zi, Zjf = (float)Zj;
        float irm = 1.0f / (radii_g[Zi] + radii_g[Zj]);
        float ia  = (powf(Zif, 0.3f) + powf(Zjf, 0.3f))
                    * (1.0f / (0.4543f * 0.529f));
        float pf  = 0.5f * 14.3996f * Zif * Zjf;
        int base = tid << 5;
#pragma unroll
        for (int c = 0; c < 32; c++) {
            s_irm[base + c] = irm;
            s_ia[base + c]  = ia;
            s_pf[base + c]  = pf;
        }
    }
    // Copy packed nibble table into smem (16B-wide, coalesced, L2-resident)
    {
        const uint4* ge = (const uint4*)g_e4;
        uint4* se = (uint4*)s_e4;
        int nvec = ((n_nodes + 1) >> 1 + 15) >> 4;
        nvec = (((n_nodes + 1) >> 1) + 15) >> 4;
        for (int w = tid; w < nvec; w += NT) se[w] = ge[w];
    }
    __syncthreads();

    const int2*   si = (const int2*)ei;
    const int2*   ri = (const int2*)(ei + n_edges);
    const float2* x2 = (const float2*)x;
    int n2 = n_edges >> 1;

    // Block-balanced contiguous chunk; threads stride NT within it.
    int q   = n2 / gridDim.x;
    int rem = n2 - q * gridDim.x;
    int b   = blockIdx.x;
    int start = b * q + (b < rem ? b : rem);
    int end   = start + q + (b < rem ? 1 : 0);

    for (int g = start + tid; g < end; g += NT) {
        int2 ss = si[g];
        int2 rr = ri[g];
        float2 xx = x2[g];
        process_edge(ss.x, rr.x, xx.x, lane, s_e4, s_irm, s_ia, s_pf, out);
        process_edge(ss.y, rr.y, xx.y, lane, s_e4, s_irm, s_ia, s_pf, out);
    }
    // scalar tail (n_edges odd)
    for (int i = (n2 << 1) + blockIdx.x * NT + tid; i < n_edges;
         i += gridDim.x * NT) {
        process_edge(ei[i], ei[n_edges + i], x[i], lane,
                     s_e4, s_irm, s_ia, s_pf, out);
    }
}

extern "C" void kernel_launch(void* const* d_in, const int* in_sizes, int n_in,
                              void* d_out, int out_size) {
    const float* x              = (const float*)d_in[0];
    const float* node_attrs     = (const float*)d_in[1];
    const int*   edge_index     = (const int*)  d_in[2];
    const int*   atomic_numbers = (const int*)  d_in[3];
    const float* covalent_radii = (const float*)d_in[4];
    float* out = (float*)d_out;

    int n_edges = in_sizes[0];            // E
    int n_nodes = in_sizes[1] / N_ELEMS;  // N

    {
        // each block covers 512 nodes / 512 outputs
        int cover = n_nodes > out_size ? n_nodes : out_size;
        int blocks = (cover + 511) / 512;
        node_prep_kernel<<<blocks, 256>>>(node_attrs, out, n_nodes, out_size);
    }

    int smem_bytes = 3 * NPAIR * 32 * (int)sizeof(float) + PACKED_N;
    cudaFuncSetAttribute(edge_kernel,
                         cudaFuncAttributeMaxDynamicSharedMemorySize,
                         smem_bytes);
    // TWO blocks/SM (88.6KB smem each), one full wave
    edge_kernel<<<EDGE_GRID, NT, smem_bytes>>>(x, edge_index, atomic_numbers,
                                               covalent_radii, out,
                                               n_edges, n_nodes);
}